// round 4
// baseline (speedup 1.0000x reference)
#include <cuda_runtime.h>
#include <cstdint>

#define HW     65536
#define BHW    131072
#define WDIM   1024
#define HDIM   64

// ---------------- global scratch ----------------
// g_acc: [0]=N1 (masked (p,k) count)  [1]=N0 (mp0 count)
// [2..5] Sum pn_a   [6..15] Sum pn_a*pn_b (a<=b: 00,01,02,03,11,12,13,22,23,33)
// [16..23] SG2  [24..31] QG2
// [32..159] interleaved: [32+2c]=SA_c [33+2c]=QA_c
__device__ float g_acc[160];
__device__ float g_wts[9 * BHW];   // softmax weights, plane-major: [k][b*HW+p]

#define PACK2(dst, f) asm("mov.b64 %0, {%1, %1};" : "=l"(dst) : "r"(__float_as_uint(f)))
#define FMA2(acc, a, b) asm("fma.rn.f32x2 %0, %1, %2, %0;" : "+l"(acc) : "l"(a), "l"(b))

// ---------------- block reduction -> atomicAdd into g_acc ----------------
template <int NV, int NW>
__device__ __forceinline__ void block_reduce_atomic(const float* vals, float* red, int tid, int accBase) {
    int lane = tid & 31, w = tid >> 5;
#pragma unroll
    for (int v = 0; v < NV; v++) {
        float r = vals[v];
#pragma unroll
        for (int o = 16; o; o >>= 1) r += __shfl_down_sync(0xffffffffu, r, o);
        if (lane == 0) red[v * NW + w] = r;
    }
    __syncthreads();
    if (tid < NV) {
        float r = 0.f;
#pragma unroll
        for (int ww = 0; ww < NW; ww++) r += red[tid * NW + ww];
        atomicAdd(&g_acc[accBase + tid], r);
    }
}

// first-layer BN affine from pn moments: var(w.pn) = w^T Cov w
__device__ __forceinline__ void affine_from_moments(const float* wrow, float gam, float bet,
                                                    float& a_out, float& b_out) {
    float n = fmaxf(g_acc[0], 1.f);
    const int qi[4][4] = {{0,1,2,3},{1,4,5,6},{2,5,7,8},{3,6,8,9}};
    float e2 = 0.f, mean = 0.f;
#pragma unroll
    for (int a = 0; a < 4; a++) {
        float wa = wrow[a];
        mean += wa * (g_acc[2 + a] / n);
        float row = 0.f;
#pragma unroll
        for (int bb = 0; bb < 4; bb++) row += wrow[bb] * (g_acc[6 + qi[a][bb]] / n);
        e2 += wa * row;
    }
    float var = e2 - mean * mean;
    float a_ = gam * rsqrtf(var + 1e-5f);
    a_out = a_;
    b_out = bet - mean * a_;
}

// ---------------- K0 ----------------
__global__ void k0_zero() {
    int t = threadIdx.x;
    if (t < 160) g_acc[t] = 0.f;
}

// ---------------- K1: pn moment stats + mask counts (tiled) ----------------
__global__ void k1_stats(const float* __restrict__ x, const float* __restrict__ mask) {
    __shared__ float tile[5 * 3 * 260];
    __shared__ float red[16 * 8];
    int tid = threadIdx.x;

    int base = blockIdx.x * 256;
    int b = base >> 16, p0 = base & (HW - 1);
    int y = p0 >> 10, x0 = p0 & (WDIM - 1);
    const float* xb0 = x + (size_t)b * 68 * HW;
    const float* mb = mask + (size_t)b * HW;

    for (int f = tid; f < 5 * 3 * 260; f += 256) {
        int pl = f / 780, rem = f - pl * 780;
        int r = rem / 260, cx = rem - r * 260;
        float v = 0.f;
        if (cx < 258) {
            int gy = y - 1 + r, gx = x0 - 1 + cx;
            if (gy >= 0 && gy < HDIM && gx >= 0 && gx < WDIM) {
                int gp = gy * WDIM + gx;
                v = (pl == 0) ? mb[gp] : xb0[(size_t)(pl - 1) * HW + gp];
            }
        }
        tile[f] = v;
    }
    __syncthreads();

    int cc = tid + 1;
    float c0 = tile[780 + 260 + cc], c1 = tile[2 * 780 + 260 + cc];
    float c2 = tile[3 * 780 + 260 + cc], c3 = tile[4 * 780 + 260 + cc];
    float cnt1 = 0.f, cnt0 = (tile[260 + cc] > 0.f) ? 1.f : 0.f;
    float s[4] = {0.f, 0.f, 0.f, 0.f};
    float q[10];
#pragma unroll
    for (int j = 0; j < 10; j++) q[j] = 0.f;

#pragma unroll
    for (int k = 0; k < 9; k++) {
        int r = k / 3, dx = k % 3 - 1;
        int tix = r * 260 + cc + dx;
        if (!(tile[tix] > 0.f)) continue;
        cnt1 += 1.f;
        float pn0 = tile[780 + tix] - c0, pn1 = tile[2 * 780 + tix] - c1;
        float pn2 = tile[3 * 780 + tix] - c2, pn3 = tile[4 * 780 + tix] - c3;
        s[0] += pn0; s[1] += pn1; s[2] += pn2; s[3] += pn3;
        q[0] += pn0 * pn0; q[1] += pn0 * pn1; q[2] += pn0 * pn2; q[3] += pn0 * pn3;
        q[4] += pn1 * pn1; q[5] += pn1 * pn2; q[6] += pn1 * pn3;
        q[7] += pn2 * pn2; q[8] += pn2 * pn3; q[9] += pn3 * pn3;
    }

    float vals[16];
    vals[0] = cnt1; vals[1] = cnt0;
#pragma unroll
    for (int a = 0; a < 4; a++) vals[2 + a] = s[a];
#pragma unroll
    for (int j = 0; j < 10; j++) vals[6 + j] = q[j];
    block_reduce_atomic<16, 8>(vals, red, tid, 0);
}

// ---------------- K2: softmax weights + gbn2 input stats (tiled, affines inlined) ----------------
__global__ void k2_wts(const float* __restrict__ x, const float* __restrict__ mask,
                       const float* __restrict__ w1, const float* __restrict__ bn1_g,
                       const float* __restrict__ bn1_b, const float* __restrict__ w2,
                       const float* __restrict__ b2, const float* __restrict__ g1,
                       const float* __restrict__ gbn1_g, const float* __restrict__ gbn1_b,
                       const float* __restrict__ g2) {
    __shared__ float tile[5 * 3 * 260];
    __shared__ float w1s[32], g1s[32], g2s[64], w2s[8], abp[32], b2sh[1];
    __shared__ float red[16 * 8];
    int tid = threadIdx.x;
    if (tid < 32) { w1s[tid] = w1[tid]; g1s[tid] = g1[tid]; }
    if (tid < 64) g2s[tid] = g2[tid];
    if (tid < 8)  w2s[tid] = w2[tid];
    if (tid == 0) b2sh[0] = b2[0];
    if (tid >= 64 && tid < 80) {
        int t2 = tid - 64;
        int path = t2 >> 3, j = t2 & 7;
        const float* wrow = (path ? g1 : w1) + j * 4;
        float gam = path ? gbn1_g[j] : bn1_g[j];
        float bet = path ? gbn1_b[j] : bn1_b[j];
        float a_, b_;
        affine_from_moments(wrow, gam, bet, a_, b_);
        abp[path * 16 + j] = a_;
        abp[path * 16 + 8 + j] = b_;
    }

    int base = blockIdx.x * 256;
    int b = base >> 16, p0 = base & (HW - 1);
    int y = p0 >> 10, x0 = p0 & (WDIM - 1);
    const float* xb0 = x + (size_t)b * 68 * HW;
    const float* mb = mask + (size_t)b * HW;

    for (int f = tid; f < 5 * 3 * 260; f += 256) {
        int pl = f / 780, rem = f - pl * 780;
        int r = rem / 260, cx = rem - r * 260;
        float v = 0.f;
        if (cx < 258) {
            int gy = y - 1 + r, gx = x0 - 1 + cx;
            if (gy >= 0 && gy < HDIM && gx >= 0 && gx < WDIM) {
                int gp = gy * WDIM + gx;
                v = (pl == 0) ? mb[gp] : xb0[(size_t)(pl - 1) * HW + gp];
            }
        }
        tile[f] = v;
    }
    __syncthreads();

    int cc = tid + 1;
    float c0 = tile[780 + 260 + cc], c1 = tile[2 * 780 + 260 + cc];
    float c2 = tile[3 * 780 + 260 + cc], c3 = tile[4 * 780 + 260 + cc];
    float logit[9];
    float sg2[8], qg2[8];
#pragma unroll
    for (int j = 0; j < 8; j++) { sg2[j] = qg2[j] = 0.f; }

#pragma unroll
    for (int k = 0; k < 9; k++) {
        int r = k / 3, dx = k % 3 - 1;
        int tix = r * 260 + cc + dx;
        float lg = 0.f;
        if (tile[tix] > 0.f) {
            float pn0 = tile[780 + tix] - c0, pn1 = tile[2 * 780 + tix] - c1;
            float pn2 = tile[3 * 780 + tix] - c2, pn3 = tile[4 * 780 + tix] - c3;
            float u[8];
            float l = b2sh[0];
#pragma unroll
            for (int j = 0; j < 8; j++) {
                float h = pn0 * w1s[j * 4] + pn1 * w1s[j * 4 + 1] + pn2 * w1s[j * 4 + 2] + pn3 * w1s[j * 4 + 3];
                float hn = fmaxf(h * abp[j] + abp[8 + j], 0.f);
                l += hn * w2s[j];
                float qv = pn0 * g1s[j * 4] + pn1 * g1s[j * 4 + 1] + pn2 * g1s[j * 4 + 2] + pn3 * g1s[j * 4 + 3];
                u[j] = fmaxf(qv * abp[16 + j] + abp[24 + j], 0.f);
            }
            lg = l;
#pragma unroll
            for (int j = 0; j < 8; j++) {
                float vv = 0.f;
#pragma unroll
                for (int m = 0; m < 8; m++) vv += u[m] * g2s[j * 8 + m];
                sg2[j] += vv; qg2[j] += vv * vv;
            }
        }
        logit[k] = lg;
    }

    float mx = logit[0];
#pragma unroll
    for (int k = 1; k < 9; k++) mx = fmaxf(mx, logit[k]);
    float s = 0.f, e[9];
#pragma unroll
    for (int k = 0; k < 9; k++) { e[k] = __expf(logit[k] - mx); s += e[k]; }
    float inv = 1.f / s;
    int i = base + tid;
#pragma unroll
    for (int k = 0; k < 9; k++) g_wts[(size_t)k * BHW + i] = e[k] * inv;

    float vals[16];
#pragma unroll
    for (int j = 0; j < 8; j++) { vals[j] = sg2[j]; vals[8 + j] = qg2[j]; }
    block_reduce_atomic<16, 8>(vals, red, tid, 16);
}

// ---------------- K3: feats -> smem, register-tiled f32x2 GEMM ----------------
// dynamic smem layout (floats): feats [0,17952) stride 132; wtile [17952,26656); mpf [26656,26784)
#define K3_FEATS   0
#define K3_WTS     17952
#define K3_MPF     26656
#define K3_SMEMF   26784

__global__ void __launch_bounds__(128) k3_main(const float* __restrict__ x, const float* __restrict__ mask,
                                               const float* __restrict__ g1, const float* __restrict__ g2,
                                               const float* __restrict__ gbn1_g, const float* __restrict__ gbn1_b,
                                               const float* __restrict__ gbn2_g, const float* __restrict__ gbn2_b,
                                               const float* __restrict__ w_agg, float* __restrict__ out) {
    extern __shared__ float sm[];
    float* feats = sm + K3_FEATS;   // [136][132]
    float* wtile = sm + K3_WTS;     // phase A: pos/mask tile (5*3*132=1980); phase B: wTs[136][64]
    float* mpf   = sm + K3_MPF;
    __shared__ float g1s[32], g2s[64], prm[32];
    int tid = threadIdx.x;

    if (tid < 32) g1s[tid] = g1[tid];
    if (tid < 64) g2s[tid] = g2[tid];
    // per-block affine derivation (g_acc final after k2; stream order guarantees it)
    if (tid < 8) {
        float a_, b_;
        affine_from_moments(g1 + tid * 4, gbn1_g[tid], gbn1_b[tid], a_, b_);
        prm[tid] = a_; prm[8 + tid] = b_;
    } else if (tid < 16) {
        int j = tid - 8;
        float n = fmaxf(g_acc[0], 1.f);
        float mean2 = g_acc[16 + j] / n;
        float var2  = g_acc[24 + j] / n - mean2 * mean2;
        float a2 = gbn2_g[j] * rsqrtf(var2 + 1e-5f);
        prm[16 + j] = a2;
        prm[24 + j] = gbn2_b[j] - mean2 * a2;
    }

    int base = blockIdx.x * 128;
    int b = base >> 16, p0 = base & (HW - 1);
    int y = p0 >> 10, x0 = p0 & (WDIM - 1);
    const float* xb0 = x + (size_t)b * 68 * HW;
    const float* mb = mask + (size_t)b * HW;

    const int TW = 132, TP = 3 * TW;
    for (int f = tid; f < 5 * TP; f += 128) {
        int pl = f / TP, rem = f - pl * TP;
        int r = rem / TW, cx = rem - r * TW;
        float v = 0.f;
        if (cx < 130) {
            int gy = y - 1 + r, gx = x0 - 1 + cx;
            if (gy >= 0 && gy < HDIM && gx >= 0 && gx < WDIM) {
                int gp = gy * WDIM + gx;
                v = (pl == 0) ? mb[gp] : xb0[(size_t)(pl - 1) * HW + gp];
            }
        }
        wtile[f] = v;
    }
    __syncthreads();

    // ---- phase A: per-pixel 136-feature vector into smem ----
    int i = base + tid;
    int p = p0 + tid;
    float wv[9];
#pragma unroll
    for (int k = 0; k < 9; k++) wv[k] = g_wts[(size_t)k * BHW + i];

    int cc = tid + 1;
    float c0 = wtile[TP + TW + cc], c1 = wtile[2 * TP + TW + cc];
    float c2 = wtile[3 * TP + TW + cc], c3 = wtile[4 * TP + TW + cc];
    mpf[tid] = (wtile[TW + cc] > 0.f) ? 1.f : 0.f;

#pragma unroll
    for (int k = 0; k < 9; k++) {
        int r = k / 3, dx = k % 3 - 1;
        int tix = r * TW + cc + dx;
        if (wtile[tix] > 0.f) {
            float pn0 = wtile[TP + tix] - c0, pn1 = wtile[2 * TP + tix] - c1;
            float pn2 = wtile[3 * TP + tix] - c2, pn3 = wtile[4 * TP + tix] - c3;
            float u[8];
#pragma unroll
            for (int j = 0; j < 8; j++) {
                float qv = pn0 * g1s[j * 4] + pn1 * g1s[j * 4 + 1] + pn2 * g1s[j * 4 + 2] + pn3 * g1s[j * 4 + 3];
                u[j] = fmaxf(qv * prm[j] + prm[8 + j], 0.f);
            }
#pragma unroll
            for (int j = 0; j < 8; j++) {
                float vv = 0.f;
#pragma unroll
                for (int m = 0; m < 8; m++) vv += u[m] * g2s[j * 8 + m];
                feats[(64 + k * 8 + j) * 132 + tid] = fmaxf(vv * prm[16 + j] + prm[24 + j], 0.f) * wv[k];
            }
        } else {
#pragma unroll
            for (int j = 0; j < 8; j++) feats[(64 + k * 8 + j) * 132 + tid] = 0.f;
        }
    }

    // fagg via warp shuffles (3 loads per channel-row instead of 9)
    int col = p & (WDIM - 1);
    int lane = tid & 31;
    bool r0ok = (y > 0), r2ok = (y < HDIM - 1);
    const float* xbp = xb0 + p;
#pragma unroll 2
    for (int c = 0; c < 64; c++) {
        const float* xc_ = xbp + (size_t)(4 + c) * HW;
        float fc = 0.f;
#pragma unroll
        for (int r = 0; r < 3; r++) {
            bool ok = (r == 1) || (r == 0 ? r0ok : r2ok);
            if (ok) {
                int roff = (r - 1) * WDIM;
                float v = xc_[roff];
                float lf = __shfl_up_sync(0xffffffffu, v, 1);
                if (lane == 0) lf = (col > 0) ? xc_[roff - 1] : 0.f;
                float rt = __shfl_down_sync(0xffffffffu, v, 1);
                if (lane == 31) rt = (col < WDIM - 1) ? xc_[roff + 1] : 0.f;
                fc += wv[r * 3] * lf + wv[r * 3 + 1] * v + wv[r * 3 + 2] * rt;
            }
        }
        feats[c * 132 + tid] = fc;
    }
    __syncthreads();

    // ---- load wTs (transposed) over the consumed tile ----
    for (int e = tid; e < 64 * 136; e += 128) {
        float v = w_agg[e];
        int o = e / 136, ii = e - o * 136;
        wtile[ii * 64 + o] = v;
    }
    __syncthreads();

    // ---- phase B: 8 px x 8 ch per thread, packed f32x2 FMA ----
    int pg = tid & 15, cg = tid >> 4;
    unsigned long long acc[32];
#pragma unroll
    for (int t = 0; t < 32; t++) acc[t] = 0ULL;

#pragma unroll 2
    for (int k = 0; k < 136; k++) {
        const float* fr = feats + k * 132 + pg * 8;
        ulonglong2 a01 = *reinterpret_cast<const ulonglong2*>(fr);
        ulonglong2 a23 = *reinterpret_cast<const ulonglong2*>(fr + 4);
        unsigned long long av0 = a01.x, av1 = a01.y, av2 = a23.x, av3 = a23.y;
        const float* wr = wtile + k * 64 + cg * 8;
        float4 w0 = *reinterpret_cast<const float4*>(wr);
        float4 w1 = *reinterpret_cast<const float4*>(wr + 4);
        unsigned long long bb[8];
        PACK2(bb[0], w0.x); PACK2(bb[1], w0.y); PACK2(bb[2], w0.z); PACK2(bb[3], w0.w);
        PACK2(bb[4], w1.x); PACK2(bb[5], w1.y); PACK2(bb[6], w1.z); PACK2(bb[7], w1.w);
#pragma unroll
        for (int c = 0; c < 8; c++) {
            FMA2(acc[c * 4 + 0], bb[c], av0);
            FMA2(acc[c * 4 + 1], bb[c], av1);
            FMA2(acc[c * 4 + 2], bb[c], av2);
            FMA2(acc[c * 4 + 3], bb[c], av3);
        }
    }

    // ---- epilogue: store raw out + abn stats ----
    int poff = pg * 8;
    float* ob = out + (size_t)b * 64 * HW + p0 + poff;
    float mm[8];
#pragma unroll
    for (int t = 0; t < 8; t++) mm[t] = mpf[poff + t];

#pragma unroll
    for (int c = 0; c < 8; c++) {
        int ch = cg * 8 + c;
        ulonglong2 s0, s1;
        s0.x = acc[c * 4]; s0.y = acc[c * 4 + 1];
        s1.x = acc[c * 4 + 2]; s1.y = acc[c * 4 + 3];
        *reinterpret_cast<ulonglong2*>(ob + (size_t)ch * HW) = s0;
        *reinterpret_cast<ulonglong2*>(ob + (size_t)ch * HW + 4) = s1;
        float sv = 0.f, qv = 0.f;
#pragma unroll
        for (int j = 0; j < 4; j++) {
            float v0 = __uint_as_float((unsigned)acc[c * 4 + j]);
            float v1 = __uint_as_float((unsigned)(acc[c * 4 + j] >> 32));
            float r0 = v0 * mm[2 * j], r1 = v1 * mm[2 * j + 1];
            sv += r0 + r1; qv += r0 * r0 + r1 * r1;
        }
#pragma unroll
        for (int o = 8; o; o >>= 1) {
            sv += __shfl_down_sync(0xffffffffu, sv, o, 16);
            qv += __shfl_down_sync(0xffffffffu, qv, o, 16);
        }
        if ((tid & 15) == 0) {
            atomicAdd(&g_acc[32 + 2 * ch], sv);
            atomicAdd(&g_acc[33 + 2 * ch], qv);
        }
    }
}

// ---------------- K4: abn normalize + relu + mask (affine inlined) ----------------
__global__ void k4_final(float* __restrict__ out, const float* __restrict__ mask,
                         const float* __restrict__ abn_g, const float* __restrict__ abn_b) {
    int t = blockIdx.x * 256 + threadIdx.x;
    int e = t * 4;
    int b = e >> 22;
    int c = (e >> 16) & 63;
    int p = e & (HW - 1);
    float n0   = fmaxf(g_acc[1], 1.f);
    float mean = g_acc[32 + 2 * c] / n0;
    float var  = g_acc[33 + 2 * c] / n0 - mean * mean;
    float a    = abn_g[c] * rsqrtf(var + 1e-5f);
    float bb   = abn_b[c] - mean * a;
    float4 v  = reinterpret_cast<float4*>(out)[t];
    float4 mk = *reinterpret_cast<const float4*>(mask + (size_t)b * HW + p);
    v.x = (mk.x > 0.f) ? fmaxf(v.x * a + bb, 0.f) : 0.f;
    v.y = (mk.y > 0.f) ? fmaxf(v.y * a + bb, 0.f) : 0.f;
    v.z = (mk.z > 0.f) ? fmaxf(v.z * a + bb, 0.f) : 0.f;
    v.w = (mk.w > 0.f) ? fmaxf(v.w * a + bb, 0.f) : 0.f;
    reinterpret_cast<float4*>(out)[t] = v;
}

// ---------------- host launcher ----------------
extern "C" void kernel_launch(void* const* d_in, const int* in_sizes, int n_in,
                              void* d_out, int out_size) {
    const float* x      = (const float*)d_in[0];
    const float* mask   = (const float*)d_in[1];
    const float* w1     = (const float*)d_in[2];
    const float* bn1_g  = (const float*)d_in[3];
    const float* bn1_b  = (const float*)d_in[4];
    const float* w2     = (const float*)d_in[5];
    const float* b2     = (const float*)d_in[6];
    const float* g1     = (const float*)d_in[7];
    const float* gbn1_g = (const float*)d_in[8];
    const float* gbn1_b = (const float*)d_in[9];
    const float* g2     = (const float*)d_in[10];
    const float* gbn2_g = (const float*)d_in[11];
    const float* gbn2_b = (const float*)d_in[12];
    const float* w_agg  = (const float*)d_in[13];
    const float* abn_g  = (const float*)d_in[14];
    const float* abn_b  = (const float*)d_in[15];
    float* out = (float*)d_out;

    cudaFuncSetAttribute(k3_main, cudaFuncAttributeMaxDynamicSharedMemorySize, K3_SMEMF * 4);

    k0_zero<<<1, 256>>>();
    k1_stats<<<BHW / 256, 256>>>(x, mask);
    k2_wts<<<BHW / 256, 256>>>(x, mask, w1, bn1_g, bn1_b, w2, b2, g1, gbn1_g, gbn1_b, g2);
    k3_main<<<BHW / 128, 128, K3_SMEMF * 4>>>(x, mask, g1, g2, gbn1_g, gbn1_b, gbn2_g, gbn2_b, w_agg, out);
    k4_final<<<(2 * 64 * HW / 4) / 256, 256>>>(out, mask, abn_g, abn_b);
}

// round 5
// speedup vs baseline: 1.7764x; 1.7764x over previous
#include <cuda_runtime.h>
#include <cstdint>

#define HW     65536
#define BHW    131072
#define WDIM   1024
#define HDIM   64

// ---------------- global scratch ----------------
// g_acc: [0]=N1 (masked (p,k) count)  [1]=N0 (mp0 count)
// [2..5] Sum pn_a   [6..15] Sum pn_a*pn_b (a<=b: 00,01,02,03,11,12,13,22,23,33)
// [16..23] SG2  [24..31] QG2
// [32..159] interleaved: [32+2c]=SA_c [33+2c]=QA_c
__device__ float g_acc[160];
__device__ float g_wts[9 * BHW];        // softmax weights, plane-major
__device__ float g_feats[136 * BHW];    // concat features, plane-major: [k][b*HW+p]

#define PACK2(dst, f) asm("mov.b64 %0, {%1, %1};" : "=l"(dst) : "r"(__float_as_uint(f)))
#define FMA2(acc, a, b) asm("fma.rn.f32x2 %0, %1, %2, %0;" : "+l"(acc) : "l"(a), "l"(b))

// ---------------- block reduction -> atomicAdd into g_acc ----------------
template <int NV, int NW>
__device__ __forceinline__ void block_reduce_atomic(const float* vals, float* red, int tid, int accBase) {
    int lane = tid & 31, w = tid >> 5;
#pragma unroll
    for (int v = 0; v < NV; v++) {
        float r = vals[v];
#pragma unroll
        for (int o = 16; o; o >>= 1) r += __shfl_down_sync(0xffffffffu, r, o);
        if (lane == 0) red[v * NW + w] = r;
    }
    __syncthreads();
    if (tid < NV) {
        float r = 0.f;
#pragma unroll
        for (int ww = 0; ww < NW; ww++) r += red[tid * NW + ww];
        atomicAdd(&g_acc[accBase + tid], r);
    }
}

// first-layer BN affine from pn moments: var(w.pn) = w^T Cov w
__device__ __forceinline__ void affine_from_moments(const float* wrow, float gam, float bet,
                                                    float& a_out, float& b_out) {
    float n = fmaxf(g_acc[0], 1.f);
    const int qi[4][4] = {{0,1,2,3},{1,4,5,6},{2,5,7,8},{3,6,8,9}};
    float e2 = 0.f, mean = 0.f;
#pragma unroll
    for (int a = 0; a < 4; a++) {
        float wa = wrow[a];
        mean += wa * (g_acc[2 + a] / n);
        float row = 0.f;
#pragma unroll
        for (int bb = 0; bb < 4; bb++) row += wrow[bb] * (g_acc[6 + qi[a][bb]] / n);
        e2 += wa * row;
    }
    float var = e2 - mean * mean;
    float a_ = gam * rsqrtf(var + 1e-5f);
    a_out = a_;
    b_out = bet - mean * a_;
}

// ---------------- K0 ----------------
__global__ void k0_zero() {
    int t = threadIdx.x;
    if (t < 160) g_acc[t] = 0.f;
}

// ---------------- K1: pn moment stats + mask counts (tiled) ----------------
__global__ void k1_stats(const float* __restrict__ x, const float* __restrict__ mask) {
    __shared__ float tile[5 * 3 * 260];
    __shared__ float red[16 * 8];
    int tid = threadIdx.x;

    int base = blockIdx.x * 256;
    int b = base >> 16, p0 = base & (HW - 1);
    int y = p0 >> 10, x0 = p0 & (WDIM - 1);
    const float* xb0 = x + (size_t)b * 68 * HW;
    const float* mb = mask + (size_t)b * HW;

    for (int f = tid; f < 5 * 3 * 260; f += 256) {
        int pl = f / 780, rem = f - pl * 780;
        int r = rem / 260, cx = rem - r * 260;
        float v = 0.f;
        if (cx < 258) {
            int gy = y - 1 + r, gx = x0 - 1 + cx;
            if (gy >= 0 && gy < HDIM && gx >= 0 && gx < WDIM) {
                int gp = gy * WDIM + gx;
                v = (pl == 0) ? mb[gp] : xb0[(size_t)(pl - 1) * HW + gp];
            }
        }
        tile[f] = v;
    }
    __syncthreads();

    int cc = tid + 1;
    float c0 = tile[780 + 260 + cc], c1 = tile[2 * 780 + 260 + cc];
    float c2 = tile[3 * 780 + 260 + cc], c3 = tile[4 * 780 + 260 + cc];
    float cnt1 = 0.f, cnt0 = (tile[260 + cc] > 0.f) ? 1.f : 0.f;
    float s[4] = {0.f, 0.f, 0.f, 0.f};
    float q[10];
#pragma unroll
    for (int j = 0; j < 10; j++) q[j] = 0.f;

#pragma unroll
    for (int k = 0; k < 9; k++) {
        int r = k / 3, dx = k % 3 - 1;
        int tix = r * 260 + cc + dx;
        if (!(tile[tix] > 0.f)) continue;
        cnt1 += 1.f;
        float pn0 = tile[780 + tix] - c0, pn1 = tile[2 * 780 + tix] - c1;
        float pn2 = tile[3 * 780 + tix] - c2, pn3 = tile[4 * 780 + tix] - c3;
        s[0] += pn0; s[1] += pn1; s[2] += pn2; s[3] += pn3;
        q[0] += pn0 * pn0; q[1] += pn0 * pn1; q[2] += pn0 * pn2; q[3] += pn0 * pn3;
        q[4] += pn1 * pn1; q[5] += pn1 * pn2; q[6] += pn1 * pn3;
        q[7] += pn2 * pn2; q[8] += pn2 * pn3; q[9] += pn3 * pn3;
    }

    float vals[16];
    vals[0] = cnt1; vals[1] = cnt0;
#pragma unroll
    for (int a = 0; a < 4; a++) vals[2 + a] = s[a];
#pragma unroll
    for (int j = 0; j < 10; j++) vals[6 + j] = q[j];
    block_reduce_atomic<16, 8>(vals, red, tid, 0);
}

// ---------------- K2: softmax weights + gbn2 input stats ----------------
__global__ void k2_wts(const float* __restrict__ x, const float* __restrict__ mask,
                       const float* __restrict__ w1, const float* __restrict__ bn1_g,
                       const float* __restrict__ bn1_b, const float* __restrict__ w2,
                       const float* __restrict__ b2, const float* __restrict__ g1,
                       const float* __restrict__ gbn1_g, const float* __restrict__ gbn1_b,
                       const float* __restrict__ g2) {
    __shared__ float tile[5 * 3 * 260];
    __shared__ float w1s[32], g1s[32], g2s[64], w2s[8], abp[32], b2sh[1];
    __shared__ float red[16 * 8];
    int tid = threadIdx.x;
    if (tid < 32) { w1s[tid] = w1[tid]; g1s[tid] = g1[tid]; }
    if (tid < 64) g2s[tid] = g2[tid];
    if (tid < 8)  w2s[tid] = w2[tid];
    if (tid == 0) b2sh[0] = b2[0];
    if (tid >= 64 && tid < 80) {
        int t2 = tid - 64;
        int path = t2 >> 3, j = t2 & 7;
        const float* wrow = (path ? g1 : w1) + j * 4;
        float gam = path ? gbn1_g[j] : bn1_g[j];
        float bet = path ? gbn1_b[j] : bn1_b[j];
        float a_, b_;
        affine_from_moments(wrow, gam, bet, a_, b_);
        abp[path * 16 + j] = a_;
        abp[path * 16 + 8 + j] = b_;
    }

    int base = blockIdx.x * 256;
    int b = base >> 16, p0 = base & (HW - 1);
    int y = p0 >> 10, x0 = p0 & (WDIM - 1);
    const float* xb0 = x + (size_t)b * 68 * HW;
    const float* mb = mask + (size_t)b * HW;

    for (int f = tid; f < 5 * 3 * 260; f += 256) {
        int pl = f / 780, rem = f - pl * 780;
        int r = rem / 260, cx = rem - r * 260;
        float v = 0.f;
        if (cx < 258) {
            int gy = y - 1 + r, gx = x0 - 1 + cx;
            if (gy >= 0 && gy < HDIM && gx >= 0 && gx < WDIM) {
                int gp = gy * WDIM + gx;
                v = (pl == 0) ? mb[gp] : xb0[(size_t)(pl - 1) * HW + gp];
            }
        }
        tile[f] = v;
    }
    __syncthreads();

    int cc = tid + 1;
    float c0 = tile[780 + 260 + cc], c1 = tile[2 * 780 + 260 + cc];
    float c2 = tile[3 * 780 + 260 + cc], c3 = tile[4 * 780 + 260 + cc];
    float logit[9];
    float sg2[8], qg2[8];
#pragma unroll
    for (int j = 0; j < 8; j++) { sg2[j] = qg2[j] = 0.f; }

#pragma unroll
    for (int k = 0; k < 9; k++) {
        int r = k / 3, dx = k % 3 - 1;
        int tix = r * 260 + cc + dx;
        float lg = 0.f;
        if (tile[tix] > 0.f) {
            float pn0 = tile[780 + tix] - c0, pn1 = tile[2 * 780 + tix] - c1;
            float pn2 = tile[3 * 780 + tix] - c2, pn3 = tile[4 * 780 + tix] - c3;
            float u[8];
            float l = b2sh[0];
#pragma unroll
            for (int j = 0; j < 8; j++) {
                float h = pn0 * w1s[j * 4] + pn1 * w1s[j * 4 + 1] + pn2 * w1s[j * 4 + 2] + pn3 * w1s[j * 4 + 3];
                float hn = fmaxf(h * abp[j] + abp[8 + j], 0.f);
                l += hn * w2s[j];
                float qv = pn0 * g1s[j * 4] + pn1 * g1s[j * 4 + 1] + pn2 * g1s[j * 4 + 2] + pn3 * g1s[j * 4 + 3];
                u[j] = fmaxf(qv * abp[16 + j] + abp[24 + j], 0.f);
            }
            lg = l;
#pragma unroll
            for (int j = 0; j < 8; j++) {
                float vv = 0.f;
#pragma unroll
                for (int m = 0; m < 8; m++) vv += u[m] * g2s[j * 8 + m];
                sg2[j] += vv; qg2[j] += vv * vv;
            }
        }
        logit[k] = lg;
    }

    float mx = logit[0];
#pragma unroll
    for (int k = 1; k < 9; k++) mx = fmaxf(mx, logit[k]);
    float s = 0.f, e[9];
#pragma unroll
    for (int k = 0; k < 9; k++) { e[k] = __expf(logit[k] - mx); s += e[k]; }
    float inv = 1.f / s;
    int i = base + tid;
#pragma unroll
    for (int k = 0; k < 9; k++) g_wts[(size_t)k * BHW + i] = e[k] * inv;

    float vals[16];
#pragma unroll
    for (int j = 0; j < 8; j++) { vals[j] = sg2[j]; vals[8 + j] = qg2[j]; }
    block_reduce_atomic<16, 8>(vals, red, tid, 16);
}

// ---------------- K3a: produce concat features -> g_feats (plane-major) ----------------
__global__ void __launch_bounds__(256) k3a_feats(const float* __restrict__ x, const float* __restrict__ mask,
                                                 const float* __restrict__ g1, const float* __restrict__ g2,
                                                 const float* __restrict__ gbn1_g, const float* __restrict__ gbn1_b,
                                                 const float* __restrict__ gbn2_g, const float* __restrict__ gbn2_b) {
    __shared__ float tile[5 * 3 * 260];
    __shared__ float g1s[32], g2s[64], prm[32];
    int tid = threadIdx.x;

    if (tid < 32) g1s[tid] = g1[tid];
    if (tid < 64) g2s[tid] = g2[tid];
    if (tid < 8) {
        float a_, b_;
        affine_from_moments(g1 + tid * 4, gbn1_g[tid], gbn1_b[tid], a_, b_);
        prm[tid] = a_; prm[8 + tid] = b_;
    } else if (tid < 16) {
        int j = tid - 8;
        float n = fmaxf(g_acc[0], 1.f);
        float mean2 = g_acc[16 + j] / n;
        float var2  = g_acc[24 + j] / n - mean2 * mean2;
        float a2 = gbn2_g[j] * rsqrtf(var2 + 1e-5f);
        prm[16 + j] = a2;
        prm[24 + j] = gbn2_b[j] - mean2 * a2;
    }

    int base = blockIdx.x * 256;
    int b = base >> 16, p0 = base & (HW - 1);
    int y = p0 >> 10, x0 = p0 & (WDIM - 1);
    const float* xb0 = x + (size_t)b * 68 * HW;
    const float* mb = mask + (size_t)b * HW;

    for (int f = tid; f < 5 * 3 * 260; f += 256) {
        int pl = f / 780, rem = f - pl * 780;
        int r = rem / 260, cx = rem - r * 260;
        float v = 0.f;
        if (cx < 258) {
            int gy = y - 1 + r, gx = x0 - 1 + cx;
            if (gy >= 0 && gy < HDIM && gx >= 0 && gx < WDIM) {
                int gp = gy * WDIM + gx;
                v = (pl == 0) ? mb[gp] : xb0[(size_t)(pl - 1) * HW + gp];
            }
        }
        tile[f] = v;
    }
    __syncthreads();

    int i = base + tid;
    float wv[9];
#pragma unroll
    for (int k = 0; k < 9; k++) wv[k] = g_wts[(size_t)k * BHW + i];

    int cc = tid + 1;
    float c0 = tile[780 + 260 + cc], c1 = tile[2 * 780 + 260 + cc];
    float c2 = tile[3 * 780 + 260 + cc], c3 = tile[4 * 780 + 260 + cc];

    // g path -> planes 64..135
#pragma unroll
    for (int k = 0; k < 9; k++) {
        int r = k / 3, dx = k % 3 - 1;
        int tix = r * 260 + cc + dx;
        if (tile[tix] > 0.f) {
            float pn0 = tile[780 + tix] - c0, pn1 = tile[2 * 780 + tix] - c1;
            float pn2 = tile[3 * 780 + tix] - c2, pn3 = tile[4 * 780 + tix] - c3;
            float u[8];
#pragma unroll
            for (int j = 0; j < 8; j++) {
                float qv = pn0 * g1s[j * 4] + pn1 * g1s[j * 4 + 1] + pn2 * g1s[j * 4 + 2] + pn3 * g1s[j * 4 + 3];
                u[j] = fmaxf(qv * prm[j] + prm[8 + j], 0.f);
            }
#pragma unroll
            for (int j = 0; j < 8; j++) {
                float vv = 0.f;
#pragma unroll
                for (int m = 0; m < 8; m++) vv += u[m] * g2s[j * 8 + m];
                g_feats[(size_t)(64 + k * 8 + j) * BHW + i] = fmaxf(vv * prm[16 + j] + prm[24 + j], 0.f) * wv[k];
            }
        } else {
#pragma unroll
            for (int j = 0; j < 8; j++) g_feats[(size_t)(64 + k * 8 + j) * BHW + i] = 0.f;
        }
    }

    // fagg via warp shuffles -> planes 0..63
    int p = p0 + tid;
    int col = p & (WDIM - 1);
    int lane = tid & 31;
    bool r0ok = (y > 0), r2ok = (y < HDIM - 1);
    const float* xbp = xb0 + p;
#pragma unroll 2
    for (int c = 0; c < 64; c++) {
        const float* xc_ = xbp + (size_t)(4 + c) * HW;
        float fc = 0.f;
#pragma unroll
        for (int r = 0; r < 3; r++) {
            bool ok = (r == 1) || (r == 0 ? r0ok : r2ok);
            if (ok) {
                int roff = (r - 1) * WDIM;
                float v = xc_[roff];
                float lf = __shfl_up_sync(0xffffffffu, v, 1);
                if (lane == 0) lf = (col > 0) ? xc_[roff - 1] : 0.f;
                float rt = __shfl_down_sync(0xffffffffu, v, 1);
                if (lane == 31) rt = (col < WDIM - 1) ? xc_[roff + 1] : 0.f;
                fc += wv[r * 3] * lf + wv[r * 3 + 1] * v + wv[r * 3 + 2] * rt;
            }
        }
        g_feats[(size_t)c * BHW + i] = fc;
    }
}

// ---------------- K3b: GEMM out = W(64x136) @ feats + abn stats ----------------
// block: 256 threads = 32 pg (x8 px) * 8 cg (x8 ch). K chunked by 8 with register prefetch.
__global__ void __launch_bounds__(256) k3b_gemm(const float* __restrict__ w_agg,
                                                const float* __restrict__ mask,
                                                float* __restrict__ out) {
    __shared__ __align__(16) float wTs[136 * 64];   // 34.8 KB, wTs[k][o]
    __shared__ __align__(16) float smf[8 * 256];    // 8 KB feats chunk
    int tid = threadIdx.x;
    int pg = tid & 31, cg = tid >> 5;

    for (int e = tid; e < 64 * 136; e += 256) {
        float v = w_agg[e];
        int o = e / 136, ii = e - o * 136;
        wTs[ii * 64 + o] = v;
    }

    int base = blockIdx.x * 256;
    int b = base >> 16, p0 = base & (HW - 1);
    const float* fb = g_feats + base;

    // prefetch chunk 0
    int r0 = tid >> 6, c4 = (tid & 63) * 4;
    float4 pre0 = *reinterpret_cast<const float4*>(fb + (size_t)r0 * BHW + c4);
    float4 pre1 = *reinterpret_cast<const float4*>(fb + (size_t)(r0 + 4) * BHW + c4);

    unsigned long long acc[32];
#pragma unroll
    for (int t = 0; t < 32; t++) acc[t] = 0ULL;

    for (int c = 0; c < 17; c++) {
        *reinterpret_cast<float4*>(&smf[r0 * 256 + c4]) = pre0;
        *reinterpret_cast<float4*>(&smf[(r0 + 4) * 256 + c4]) = pre1;
        __syncthreads();
        if (c < 16) {
            const float* nf = fb + (size_t)(c + 1) * 8 * BHW;
            pre0 = *reinterpret_cast<const float4*>(nf + (size_t)r0 * BHW + c4);
            pre1 = *reinterpret_cast<const float4*>(nf + (size_t)(r0 + 4) * BHW + c4);
        }
#pragma unroll
        for (int kk = 0; kk < 8; kk++) {
            const float* fr = smf + kk * 256 + pg * 8;
            ulonglong2 a01 = *reinterpret_cast<const ulonglong2*>(fr);
            ulonglong2 a23 = *reinterpret_cast<const ulonglong2*>(fr + 4);
            unsigned long long av0 = a01.x, av1 = a01.y, av2 = a23.x, av3 = a23.y;
            const float* wr = wTs + (c * 8 + kk) * 64 + cg * 8;
            float4 w0 = *reinterpret_cast<const float4*>(wr);
            float4 w1 = *reinterpret_cast<const float4*>(wr + 4);
            unsigned long long bb[8];
            PACK2(bb[0], w0.x); PACK2(bb[1], w0.y); PACK2(bb[2], w0.z); PACK2(bb[3], w0.w);
            PACK2(bb[4], w1.x); PACK2(bb[5], w1.y); PACK2(bb[6], w1.z); PACK2(bb[7], w1.w);
#pragma unroll
            for (int ch = 0; ch < 8; ch++) {
                FMA2(acc[ch * 4 + 0], bb[ch], av0);
                FMA2(acc[ch * 4 + 1], bb[ch], av1);
                FMA2(acc[ch * 4 + 2], bb[ch], av2);
                FMA2(acc[ch * 4 + 3], bb[ch], av3);
            }
        }
        __syncthreads();
    }

    // epilogue: store raw out + abn stats (mask center from global, coalesced/broadcast)
    const float* mp = mask + (size_t)b * HW + p0 + pg * 8;
    float4 m0 = *reinterpret_cast<const float4*>(mp);
    float4 m1 = *reinterpret_cast<const float4*>(mp + 4);
    float mm[8] = { m0.x > 0.f ? 1.f : 0.f, m0.y > 0.f ? 1.f : 0.f,
                    m0.z > 0.f ? 1.f : 0.f, m0.w > 0.f ? 1.f : 0.f,
                    m1.x > 0.f ? 1.f : 0.f, m1.y > 0.f ? 1.f : 0.f,
                    m1.z > 0.f ? 1.f : 0.f, m1.w > 0.f ? 1.f : 0.f };

    float* ob = out + (size_t)b * 64 * HW + p0 + pg * 8;
#pragma unroll
    for (int ch = 0; ch < 8; ch++) {
        int o = cg * 8 + ch;
        ulonglong2 s0, s1;
        s0.x = acc[ch * 4]; s0.y = acc[ch * 4 + 1];
        s1.x = acc[ch * 4 + 2]; s1.y = acc[ch * 4 + 3];
        *reinterpret_cast<ulonglong2*>(ob + (size_t)o * HW) = s0;
        *reinterpret_cast<ulonglong2*>(ob + (size_t)o * HW + 4) = s1;
        float sv = 0.f, qv = 0.f;
#pragma unroll
        for (int j = 0; j < 4; j++) {
            float v0 = __uint_as_float((unsigned)acc[ch * 4 + j]);
            float v1 = __uint_as_float((unsigned)(acc[ch * 4 + j] >> 32));
            float t0 = v0 * mm[2 * j], t1 = v1 * mm[2 * j + 1];
            sv += t0 + t1; qv += t0 * t0 + t1 * t1;
        }
#pragma unroll
        for (int o2 = 16; o2; o2 >>= 1) {
            sv += __shfl_down_sync(0xffffffffu, sv, o2);
            qv += __shfl_down_sync(0xffffffffu, qv, o2);
        }
        if (pg == 0) {
            atomicAdd(&g_acc[32 + 2 * o], sv);
            atomicAdd(&g_acc[33 + 2 * o], qv);
        }
    }
}

// ---------------- K4: abn normalize + relu + mask ----------------
__global__ void k4_final(float* __restrict__ out, const float* __restrict__ mask,
                         const float* __restrict__ abn_g, const float* __restrict__ abn_b) {
    int t = blockIdx.x * 256 + threadIdx.x;
    int e = t * 4;
    int b = e >> 22;
    int c = (e >> 16) & 63;
    int p = e & (HW - 1);
    float n0   = fmaxf(g_acc[1], 1.f);
    float mean = g_acc[32 + 2 * c] / n0;
    float var  = g_acc[33 + 2 * c] / n0 - mean * mean;
    float a    = abn_g[c] * rsqrtf(var + 1e-5f);
    float bb   = abn_b[c] - mean * a;
    float4 v  = reinterpret_cast<float4*>(out)[t];
    float4 mk = *reinterpret_cast<const float4*>(mask + (size_t)b * HW + p);
    v.x = (mk.x > 0.f) ? fmaxf(v.x * a + bb, 0.f) : 0.f;
    v.y = (mk.y > 0.f) ? fmaxf(v.y * a + bb, 0.f) : 0.f;
    v.z = (mk.z > 0.f) ? fmaxf(v.z * a + bb, 0.f) : 0.f;
    v.w = (mk.w > 0.f) ? fmaxf(v.w * a + bb, 0.f) : 0.f;
    reinterpret_cast<float4*>(out)[t] = v;
}

// ---------------- host launcher ----------------
extern "C" void kernel_launch(void* const* d_in, const int* in_sizes, int n_in,
                              void* d_out, int out_size) {
    const float* x      = (const float*)d_in[0];
    const float* mask   = (const float*)d_in[1];
    const float* w1     = (const float*)d_in[2];
    const float* bn1_g  = (const float*)d_in[3];
    const float* bn1_b  = (const float*)d_in[4];
    const float* w2     = (const float*)d_in[5];
    const float* b2     = (const float*)d_in[6];
    const float* g1     = (const float*)d_in[7];
    const float* gbn1_g = (const float*)d_in[8];
    const float* gbn1_b = (const float*)d_in[9];
    const float* g2     = (const float*)d_in[10];
    const float* gbn2_g = (const float*)d_in[11];
    const float* gbn2_b = (const float*)d_in[12];
    const float* w_agg  = (const float*)d_in[13];
    const float* abn_g  = (const float*)d_in[14];
    const float* abn_b  = (const float*)d_in[15];
    float* out = (float*)d_out;

    k0_zero<<<1, 256>>>();
    k1_stats<<<BHW / 256, 256>>>(x, mask);
    k2_wts<<<BHW / 256, 256>>>(x, mask, w1, bn1_g, bn1_b, w2, b2, g1, gbn1_g, gbn1_b, g2);
    k3a_feats<<<BHW / 256, 256>>>(x, mask, g1, g2, gbn1_g, gbn1_b, gbn2_g, gbn2_b);
    k3b_gemm<<<BHW / 256, 256>>>(w_agg, mask, out);
    k4_final<<<(2 * 64 * HW / 4) / 256, 256>>>(out, mask, abn_g, abn_b);
}